// round 16
// baseline (speedup 1.0000x reference)
#include <cuda_runtime.h>
#include <math.h>
#include <stdint.h>

// Problem dims
#define LL  4
#define BB  2
#define SSq 512
#define MMm 512
#define DDd 1024
#define HHh 16
#define DKk 64
#define FFf 4096
#define TTt (SSq + MMm)   // 1024
#define NZ  4             // attention T-split factor

// ---------------- scratch ----------------
__device__ float g_pos[TTt * DDd];        // tf32 bits
__device__ float g_q  [BB * SSq * DDd];   // fp32
__device__ float g_kl [LL * BB * TTt * DDd];  // tf32, per-layer K
__device__ float g_vl [LL * BB * TTt * DDd];  // tf32, per-layer V [b][t][h*64+dk]
__device__ float g_vtl[LL * BB * HHh * DKk * TTt]; // tf32, per-layer V^T [b][h][dk][t]
__device__ float g_rl [LL * TTt * DDd];   // tf32, per-layer R
__device__ float g_attn[BB * SSq * DDd];  // tf32 bits
__device__ float g_tmp [BB * SSq * DDd];
__device__ float g_tmp2[BB * SSq * DDd];
__device__ float g_tmp3[BB * SSq * DDd];
__device__ float g_tmp4[BB * SSq * DDd];
__device__ float g_pm [NZ * BB * HHh * SSq];
__device__ float g_ps [NZ * BB * HHh * SSq];
__device__ float g_ff  [BB * SSq * FFf];  // tf32 bits
__device__ float g_h   [BB * SSq * DDd];  // fp32 residual
__device__ float g_hc  [BB * SSq * DDd];  // tf32 copy
__device__ float g_h1  [BB * SSq * DDd];  // fp32 residual
__device__ float g_h1c [BB * SSq * DDd];  // tf32 copy
// pre-converted operands (tf32 bits)
__device__ float g_wqc[LL * DDd * DDd];
__device__ float g_wkc[LL * DDd * DDd];
__device__ float g_wvc[LL * DDd * DDd];
__device__ float g_wrc[LL * DDd * DDd];
__device__ float g_woc[LL * DDd * DDd];
__device__ float g_w1c[LL * DDd * FFf];
__device__ float g_w2c[LL * FFf * DDd];
__device__ float g_memc[LL * BB * MMm * DDd];
__device__ float g_xc  [BB * SSq * DDd];

// ---------------- PTX helpers ----------------
__device__ __forceinline__ uint32_t f2tf32(float f) {
    uint32_t u;
    asm("cvt.rna.tf32.f32 %0, %1;" : "=r"(u) : "f"(f));
    return u;
}
__device__ __forceinline__ void mma_tf32(float c[4], const uint32_t a[4], const uint32_t b[2]) {
    asm volatile(
        "mma.sync.aligned.m16n8k8.row.col.f32.tf32.tf32.f32 "
        "{%0,%1,%2,%3},{%4,%5,%6,%7},{%8,%9},{%0,%1,%2,%3};"
        : "+f"(c[0]), "+f"(c[1]), "+f"(c[2]), "+f"(c[3])
        : "r"(a[0]), "r"(a[1]), "r"(a[2]), "r"(a[3]), "r"(b[0]), "r"(b[1]));
}
__device__ __forceinline__ void cp_async16(void* smem, const void* g) {
    uint32_t s = (uint32_t)__cvta_generic_to_shared(smem);
    asm volatile("cp.async.cg.shared.global [%0], [%1], 16;" :: "r"(s), "l"(g));
}
#define CP_COMMIT() asm volatile("cp.async.commit_group;")
#define CP_WAIT(n)  asm volatile("cp.async.wait_group %0;" :: "n"(n))

__device__ __forceinline__ uint32_t sm_u32(const void* p) {
    return (uint32_t)__cvta_generic_to_shared(p);
}
__device__ __forceinline__ void ldsm_x4(uint32_t r[4], uint32_t addr) {
    asm volatile("ldmatrix.sync.aligned.m8n8.x4.shared.b16 {%0,%1,%2,%3}, [%4];"
                 : "=r"(r[0]), "=r"(r[1]), "=r"(r[2]), "=r"(r[3]) : "r"(addr));
}
__device__ __forceinline__ void ldsm_x2(uint32_t r[2], uint32_t addr) {
    asm volatile("ldmatrix.sync.aligned.m8n8.x2.shared.b16 {%0,%1}, [%2];"
                 : "=r"(r[0]), "=r"(r[1]) : "r"(addr));
}

// ---------------- flattened 9-region fp32 -> tf32-bit convert ----------------
struct CvtP {
    const float* in[9];
    float* out[9];
    int cum[10];
};
__global__ void cvt_all9(CvtP p)
{
    int blk = blockIdx.x;
    int r = 0;
#pragma unroll
    for (int j = 1; j < 9; j++) r += (blk >= p.cum[j]);
    int i = (blk - p.cum[r]) * 256 + threadIdx.x;
    float4 v = ((const float4*)p.in[r])[i];
    uint4 u = make_uint4(f2tf32(v.x), f2tf32(v.y), f2tf32(v.z), f2tf32(v.w));
    ((uint4*)p.out[r])[i] = u;
}

// ---------------- positional encodings (tf32 out) ----------------
__global__ void pos_kernel(float* __restrict__ pos)
{
    int idx = blockIdx.x * blockDim.x + threadIdx.x;
    if (idx >= TTt * (DDd / 2)) return;
    int t = idx / (DDd / 2), j = idx % (DDd / 2);
    double invf = exp(((double)(-2 * j) / (double)DDd) * 9.210340371976184);
    double ang  = (double)(TTt - 1 - t) * invf;
    double kk   = floor(ang * 0.15915494309189535);
    float a = (float)(ang - kk * 6.283185307179586);
    pos[(size_t)t * DDd + j]           = __uint_as_float(f2tf32(sinf(a)));
    pos[(size_t)t * DDd + j + DDd / 2] = __uint_as_float(f2tf32(cosf(a)));
}

// ---------------- V transpose helpers ----------------
__device__ __forceinline__ void vtrans_tile(const float* __restrict__ v, float* __restrict__ vt,
                                            int b, int h, int bh, int t0, int d0)
{
    __shared__ float tile[32][33];
    int tx = threadIdx.x, ty = threadIdx.y;   // 32 x 8
#pragma unroll
    for (int j = 0; j < 4; j++) {
        int t = t0 + ty + j * 8;
        tile[ty + j * 8][tx] = v[((size_t)b * TTt + t) * DDd + h * DKk + d0 + tx];
    }
    __syncthreads();
#pragma unroll
    for (int j = 0; j < 4; j++) {
        int d = d0 + ty + j * 8;
        vt[((size_t)bh * DKk + d) * TTt + t0 + tx] = tile[tx][ty + j * 8];
    }
}

// static half: mem rows (t < 512), all layers. grid (16, 2, LL*32)
__global__ void vtrans_static(const float* __restrict__ vl, float* __restrict__ vtl)
{
    int z = blockIdx.z;
    int l = z >> 5, bh = z & 31;
    int b = bh >> 4, h = bh & 15;
    vtrans_tile(vl + (size_t)l * BB * TTt * DDd,
                vtl + (size_t)l * BB * HHh * DKk * TTt,
                b, h, bh, blockIdx.x * 32, blockIdx.y * 32);
}

// dynamic half: h rows (t >= 512), one layer. grid (16, 2, 32)
__global__ void vtrans_dyn(const float* __restrict__ v, float* __restrict__ vt)
{
    int bh = blockIdx.z;
    int b = bh >> 4, h = bh & 15;
    vtrans_tile(v, vt, b, h, bh, SSq + blockIdx.x * 32, blockIdx.y * 32);
}

// ======================================================================
// Async GEMM core (R9 verified): pre-converted tf32 operands.
// ======================================================================
template<int BM, int NWN>
__device__ __forceinline__ void gemm_core_async(
    const float* __restrict__ Ag, const float* __restrict__ Bg, float* __restrict__ Cg,
    int N, int K, int lda, float alpha, const float* __restrict__ biasg, int relu,
    int cvt_out)
{
    constexpr int BN = NWN * 32;
    constexpr int NWM = 8 / NWN;
    constexpr int WM = BM / NWM;
    constexpr int MT = WM / 16;
    constexpr int BPITCH = BN + 8;
    constexpr int NA_CH = BM / 64;
    constexpr int NB_CH = BN / 64;

    __shared__ uint32_t As[2][BM][20];
    __shared__ uint32_t Bs[2][16][BPITCH];

    int tid = threadIdx.x, lane = tid & 31, warp = tid >> 5;
    int g = lane >> 2, tg = lane & 3;
    int warp_m = warp % NWM, warp_n = warp / NWM;
    int wm = warp_m * WM, wn = warp_n * 32;

    float acc[MT][4][4];
#pragma unroll
    for (int mt = 0; mt < MT; mt++)
#pragma unroll
        for (int nt = 0; nt < 4; nt++)
#pragma unroll
            for (int i = 0; i < 4; i++) acc[mt][nt][i] = 0.f;

    int ar[NA_CH], ak[NA_CH];
#pragma unroll
    for (int j = 0; j < NA_CH; j++) {
        int c = tid + j * 256;
        ar[j] = c >> 2; ak[j] = (c & 3) * 4;
    }
    int bk[NB_CH], bn[NB_CH];
#pragma unroll
    for (int j = 0; j < NB_CH; j++) {
        int c = tid + j * 256;
        if (BN == 128) { bk[j] = c >> 5; bn[j] = (c & 31) * 4; }
        else           { bk[j] = c >> 4; bn[j] = (c & 15) * 4; }
    }

    int nk = K / 16;

#pragma unroll
    for (int j = 0; j < NA_CH; j++)
        cp_async16(&As[0][ar[j]][ak[j]], Ag + (size_t)ar[j] * lda + ak[j]);
#pragma unroll
    for (int j = 0; j < NB_CH; j++)
        cp_async16(&Bs[0][bk[j]][bn[j]], Bg + (size_t)bk[j] * N + bn[j]);
    CP_COMMIT();

    for (int kt = 0; kt < nk; kt++) {
        int buf = kt & 1;
        bool more = (kt + 1 < nk);
        if (more) {
            int nb = buf ^ 1;
#pragma unroll
            for (int j = 0; j < NA_CH; j++)
                cp_async16(&As[nb][ar[j]][ak[j]],
                           Ag + (size_t)ar[j] * lda + (kt + 1) * 16 + ak[j]);
#pragma unroll
            for (int j = 0; j < NB_CH; j++)
                cp_async16(&Bs[nb][bk[j]][bn[j]],
                           Bg + (size_t)((kt + 1) * 16 + bk[j]) * N + bn[j]);
            CP_COMMIT();
            CP_WAIT(1);
        } else {
            CP_WAIT(0);
        }
        __syncthreads();

#pragma unroll
        for (int ks = 0; ks < 2; ks++) {
            uint32_t af[MT][4], bf[4][2];
#pragma unroll
            for (int mt = 0; mt < MT; mt++) {
                int row = wm + mt * 16;
                af[mt][0] = As[buf][row + g][ks * 8 + tg];
                af[mt][1] = As[buf][row + g + 8][ks * 8 + tg];
                af[mt][2] = As[buf][row + g][ks * 8 + tg + 4];
                af[mt][3] = As[buf][row + g + 8][ks * 8 + tg + 4];
            }
#pragma unroll
            for (int nt = 0; nt < 4; nt++) {
                int col = wn + nt * 8 + g;
                bf[nt][0] = Bs[buf][ks * 8 + tg][col];
                bf[nt][1] = Bs[buf][ks * 8 + tg + 4][col];
            }
#pragma unroll
            for (int mt = 0; mt < MT; mt++)
#pragma unroll
                for (int nt = 0; nt < 4; nt++) mma_tf32(acc[mt][nt], af[mt], bf[nt]);
        }
        if (more) __syncthreads();
    }

#pragma unroll
    for (int mt = 0; mt < MT; mt++) {
#pragma unroll
        for (int nt = 0; nt < 4; nt++) {
            int row = wm + mt * 16 + g;
            int col = wn + nt * 8 + tg * 2;
            float bx0 = 0.f, bx1 = 0.f;
            if (biasg) { bx0 = biasg[col]; bx1 = biasg[col + 1]; }
            float v0 = acc[mt][nt][0] * alpha + bx0;
            float v1 = acc[mt][nt][1] * alpha + bx1;
            float v2 = acc[mt][nt][2] * alpha + bx0;
            float v3 = acc[mt][nt][3] * alpha + bx1;
            if (relu) {
                v0 = fmaxf(v0, 0.f); v1 = fmaxf(v1, 0.f);
                v2 = fmaxf(v2, 0.f); v3 = fmaxf(v3, 0.f);
            }
            if (cvt_out) {
                v0 = __uint_as_float(f2tf32(v0));
                v1 = __uint_as_float(f2tf32(v1));
                v2 = __uint_as_float(f2tf32(v2));
                v3 = __uint_as_float(f2tf32(v3));
            }
            *(float2*)(Cg + (size_t)row * N + col)       = make_float2(v0, v1);
            *(float2*)(Cg + (size_t)(row + 8) * N + col) = make_float2(v2, v3);
        }
    }
}

template<int BM, int NWN>
__global__ void __launch_bounds__(256) tc_gemm_k(
    const float* __restrict__ A, const float* __restrict__ B, float* __restrict__ C,
    int N, int K, float alpha, const float* __restrict__ bias, int relu, int cvt_out)
{
    constexpr int BN = NWN * 32;
    const float* Ag = A + (size_t)blockIdx.y * BM * K;
    const float* Bg = B + (size_t)blockIdx.x * BN;
    float* Cg = C + (size_t)blockIdx.y * BM * N + (size_t)blockIdx.x * BN;
    const float* bg = bias ? bias + (size_t)blockIdx.x * BN : nullptr;
    gemm_core_async<BM, NWN>(Ag, Bg, Cg, N, K, K, alpha, bg, relu, cvt_out);
}

template<int BM, int NWN>
__global__ void __launch_bounds__(256) tc_gemm_splitk(
    const float* __restrict__ A, const float* __restrict__ B,
    float* __restrict__ C0, float* __restrict__ C1,
    int N, int K, const float* __restrict__ bias)
{
    constexpr int BN = NWN * 32;
    int z = blockIdx.z;
    int K2 = K >> 1;
    const float* Ag = A + (size_t)blockIdx.y * BM * K + (size_t)z * K2;
    const float* Bg = B + (size_t)z * K2 * N + (size_t)blockIdx.x * BN;
    float* C = z ? C1 : C0;
    float* Cg = C + (size_t)blockIdx.y * BM * N + (size_t)blockIdx.x * BN;
    const float* bg = (bias && z == 0) ? bias + (size_t)blockIdx.x * BN : nullptr;
    gemm_core_async<BM, NWN>(Ag, Bg, Cg, N, K2, K, 1.f, bg, 0, 0);
}

// ---------------- upfront static projections: k-mem, v-mem, r for ALL layers ----------
// grid (8, LL*24): y -> l = y/24, yy = y%24.
// yy<8: r | yy in [8,16): k-mem | yy in [16,24): v-mem
__global__ void __launch_bounds__(256) grouped_static(
    const float* __restrict__ memc, const float* __restrict__ pos,
    const float* __restrict__ wkc, const float* __restrict__ wvc, const float* __restrict__ wrc,
    float* __restrict__ kl, float* __restrict__ vl, float* __restrict__ rl)
{
    int y = blockIdx.y;
    int l = y / 24, yy = y % 24;
    const float* Ag; const float* B; float* C;
    if (yy < 8) {
        Ag = pos + (size_t)yy * 128 * DDd;
        B  = wrc + (size_t)l * DDd * DDd;
        C  = rl + (size_t)l * TTt * DDd + (size_t)yy * 128 * DDd;
    } else {
        int idx = yy & 7;               // 0..7
        int b = idx >> 2, t0 = (idx & 3) * 128;   // mem rows [0, 512)
        Ag = memc + (size_t)l * BB * MMm * DDd + ((size_t)b * MMm + t0) * DDd;
        if (yy < 16) {
            B = wkc + (size_t)l * DDd * DDd;
            C = kl + (size_t)l * BB * TTt * DDd + ((size_t)b * TTt + t0) * DDd;
        } else {
            B = wvc + (size_t)l * DDd * DDd;
            C = vl + (size_t)l * BB * TTt * DDd + ((size_t)b * TTt + t0) * DDd;
        }
    }
    const float* Bg = B + (size_t)blockIdx.x * 128;
    float* Cg = C + (size_t)blockIdx.x * 128;
    gemm_core_async<128, 4>(Ag, Bg, Cg, DDd, DDd, DDd, 1.f, nullptr, 0, 1);
}

// ---------------- per-layer dynamic projections: q, k-h, v-h ----------
// grid (8, 24): y<8 q | [8,16) k-h | [16,24) v-h
__global__ void __launch_bounds__(256) grouped_dyn(
    const float* __restrict__ hcc,
    const float* __restrict__ Wq, const float* __restrict__ Wk, const float* __restrict__ Wv,
    float* __restrict__ q, float* __restrict__ k, float* __restrict__ v)
{
    int y = blockIdx.y;
    const float* Ag; const float* B; float* C; float alpha = 1.f; int cvt = 1;
    if (y < 8) {
        Ag = hcc + (size_t)y * 128 * DDd; B = Wq; C = q + (size_t)y * 128 * DDd;
        alpha = 0.125f; cvt = 0;
    } else {
        int idx = y & 7;
        int b = idx >> 2, s0 = (idx & 3) * 128;
        Ag = hcc + ((size_t)b * SSq + s0) * DDd;
        if (y < 16) { B = Wk; C = k + ((size_t)b * TTt + SSq + s0) * DDd; }
        else        { B = Wv; C = v + ((size_t)b * TTt + SSq + s0) * DDd; }
    }
    const float* Bg = B + (size_t)blockIdx.x * 128;
    float* Cg = C + (size_t)blockIdx.x * 128;
    gemm_core_async<128, 4>(Ag, Bg, Cg, DDd, DDd, DDd, alpha, nullptr, 0, cvt);
}

// ======================================================================
// Flash fused attention, split over T into NZ partitions (R14 verified).
// ======================================================================
#define SMT   32
#define TN    64
#define QPITCH 68
#define WPITCH 100
#define SMEM_ATTN_FLOATS (2*SMT*QPITCH + 64*QPITCH + 96*QPITCH + 64*QPITCH + SMT*QPITCH + SMT*WPITCH + 96)
#define SMEM_ATTN_BYTES  (SMEM_ATTN_FLOATS * 4)

__global__ void __launch_bounds__(256) fused_attn_split(
    const float* __restrict__ q, const float* __restrict__ k, const float* __restrict__ vt,
    const float* __restrict__ r, const float* __restrict__ rwb, const float* __restrict__ rrb,
    float* __restrict__ o0, float* __restrict__ o1,
    float* __restrict__ o2, float* __restrict__ o3,
    float* __restrict__ pm, float* __restrict__ ps)
{
    extern __shared__ float sm[];
    uint32_t* Qcb  = (uint32_t*)sm;
    uint32_t* Qrb  = Qcb + SMT * QPITCH;
    uint32_t* Ktb  = Qrb + SMT * QPITCH;
    uint32_t* Rwb  = Ktb + 64 * QPITCH;
    uint32_t* Vtb  = Rwb + 96 * QPITCH;   // [64 dk][68 t]
    float*    Lt   = (float*)(Vtb + 64 * QPITCH);
    float*    QRW  = Lt + SMT * QPITCH;
    float*    crow = QRW + SMT * WPITCH;
    float*    rowm = crow + 32;
    float*    rowsum = rowm + 32;
    uint32_t* Ltb  = (uint32_t*)Lt;

    int tid = threadIdx.x, lane = tid & 31, warp = tid >> 5;
    int g = lane >> 2, tg = lane & 3;
    int s0 = (15 - blockIdx.x) * SMT;
    int b = blockIdx.y >> 4, h = blockIdx.y & 15;
    int z = blockIdx.z;

    const float* qb = q + (size_t)b * SSq * DDd + h * DKk;
    const float* kb = k + (size_t)b * TTt * DDd + h * DKk;
    const float* vtb = vt + (size_t)(b * HHh + h) * DKk * TTt;
    const float* rb = r + h * DKk;
    const float* wbv = rwb + h * DKk;
    const float* rbv = rrb + h * DKk;

    int ntiles = (s0 + 543) / 64 + 1;
    int tbeg = (z * ntiles) / NZ;
    int tend = ((z + 1) * ntiles) / NZ;

    int lrow = tid >> 4, lk0 = (tid & 15) * 4;

    auto issue_KR = [&](int it) {
        if (it < tend) {
            int t0 = it * TN, jb = t0 - s0 + 480;
#pragma unroll
            for (int j = 0; j < 4; j++) {
                int row = lrow + j * 16;
                cp_async16(&Ktb[row * QPITCH + lk0], kb + (size_t)(t0 + row) * DDd + lk0);
            }
#pragma unroll
            for (int j = 0; j < 6; j++) {
                int row = lrow + j * 16;
                int jg = jb + row;
                if (jg > TTt - 1) jg = TTt - 1;
                if (jg < 0) jg = 0;
                cp_async16(&Rwb[row * QPITCH + lk0], rb + (size_t)jg * DDd + lk0);
            }
        }
        CP_COMMIT();
    };
    auto issue_V = [&](int it) {
        if (it < tend) {
            int t0 = it * TN;
#pragma unroll
            for (int j = 0; j < 4; j++) {
                int row = lrow + j * 16;
                cp_async16(&Vtb[row * QPITCH + lk0], vtb + (size_t)row * TTt + t0 + lk0);
            }
        }
        CP_COMMIT();
    };

    issue_KR(tbeg);

#pragma unroll
    for (int j = 0; j < 2; j++) {
        int c = tid + j * 256;
        int row = c >> 4, k0 = (c & 15) * 4;
        float4 qv = *(const float4*)(qb + (size_t)(s0 + row) * DDd + k0);
        float4 w4 = *(const float4*)(wbv + k0);
        float4 r4 = *(const float4*)(rbv + k0);
        Qcb[row * QPITCH + k0 + 0] = f2tf32(qv.x + w4.x);
        Qcb[row * QPITCH + k0 + 1] = f2tf32(qv.y + w4.y);
        Qcb[row * QPITCH + k0 + 2] = f2tf32(qv.z + w4.z);
        Qcb[row * QPITCH + k0 + 3] = f2tf32(qv.w + w4.w);
        Qrb[row * QPITCH + k0 + 0] = f2tf32(qv.x + r4.x);
        Qrb[row * QPITCH + k0 + 1] = f2tf32(qv.y + r4.y);
        Qrb[row * QPITCH + k0 + 2] = f2tf32(qv.z + r4.z);
        Qrb[row * QPITCH + k0 + 3] = f2tf32(qv.w + r4.w);
    }
    if (tid < 32) { rowm[tid] = -1e30f; rowsum[tid] = 0.f; }

    int wm2 = (warp & 1) * 16;
    int wn2 = (warp >> 1) * 16;
    int wn3 = (warp >> 1) * 24;
    int r1 = wm2 + g, r2 = r1 + 8;

    int srow = warp * 4 + (lane >> 3);
    int scol = (lane & 7) * 8;

    int a_row = (lane & 7) + ((lane >> 3) & 1) * 8;
    int a_col = (lane >> 4) * 4;
    int b_row = (lane & 7) + ((lane >> 4) & 1) * 8;
    int b_col = ((lane >> 3) & 1) * 4;
    int c_row = lane & 7;
    int c_col = ((lane >> 3) & 1) * 4;

    uint32_t qc_a  = sm_u32(&Qcb[(wm2 + a_row) * QPITCH + a_col]);
    uint32_t qr_a  = sm_u32(&Qrb[(wm2 + a_row) * QPITCH + a_col]);
    uint32_t lt_a  = sm_u32(&Ltb[(wm2 + a_row) * QPITCH + a_col]);
    uint32_t kt_a  = sm_u32(&Ktb[(wn2 + b_row) * QPITCH + b_col]);
    uint32_t vt_a  = sm_u32(&Vtb[(wn2 + b_row) * QPITCH + b_col]);
    uint32_t rw4_a = sm_u32(&Rwb[(wn3 + b_row) * QPITCH + b_col]);
    uint32_t rw2_a = sm_u32(&Rwb[(wn3 + 16 + c_row) * QPITCH + c_col]);

    float oacc[2][4];
#pragma unroll
    for (int nt = 0; nt < 2; nt++)
#pragma unroll
        for (int i = 0; i < 4; i++) oacc[nt][i] = 0.f;

    for (int it = tbeg; it < tend; it++) {
        int t0 = it * TN;
        CP_WAIT(0);
        __syncthreads();     // sync A

        issue_V(it);

        float ca[2][4], ra[3][4];
#pragma unroll
        for (int nt = 0; nt < 2; nt++)
#pragma unroll
            for (int i = 0; i < 4; i++) ca[nt][i] = 0.f;
#pragma unroll
        for (int nt = 0; nt < 3; nt++)
#pragma unroll
            for (int i = 0; i < 4; i++) ra[nt][i] = 0.f;

#pragma unroll
        for (int k8 = 0; k8 < 64; k8 += 8) {
            uint32_t koff = k8 * 4;
            uint32_t af[4], afr[4], bk4[4], br4[4], br2[2];
            ldsm_x4(af,  qc_a + koff);
            ldsm_x4(afr, qr_a + koff);
            ldsm_x4(bk4, kt_a + koff);
            ldsm_x4(br4, rw4_a + koff);
            ldsm_x2(br2, rw2_a + koff);
            {
                uint32_t bf0[2] = {bk4[0], bk4[1]};
                uint32_t bf1[2] = {bk4[2], bk4[3]};
                mma_tf32(ca[0], af, bf0);
                mma_tf32(ca[1], af, bf1);
            }
            {
                uint32_t bf0[2] = {br4[0], br4[1]};
                uint32_t bf1[2] = {br4[2], br4[3]};
                mma_tf32(ra[0], afr, bf0);
                mma_tf32(ra[1], afr, bf1);
                mma_tf32(ra[2], afr, br2);
            }
        }
#pragma unroll
        for (int nt = 0; nt < 2; nt++) {
            int c0 = wn2 + nt * 8 + tg * 2;
            Lt[r1 * QPITCH + c0]     = ca[nt][0];
            Lt[r1 * QPITCH + c0 + 1] = ca[nt][1];
            Lt[r2 * QPITCH + c0]     = ca[nt][2];
            Lt[r2 * QPITCH + c0 + 1] = ca[nt][3];
        }
#pragma unroll
        for (int nt = 0; nt < 3; nt++) {
            int c0 = wn3 + nt * 8 + tg * 2;
            QRW[r1 * WPITCH + c0]     = ra[nt][0];
            QRW[r1 * WPITCH + c0 + 1] = ra[nt][1];
            QRW[r2 * WPITCH + c0]     = ra[nt][2];
            QRW[r2 * WPITCH + c0 + 1] = ra[nt][3];
        }
        __syncthreads();     // sync B

        issue_KR(it + 1);

        // warp-exclusive row softmax
        {
            float4 ca4 = *(const float4*)&Lt[srow * QPITCH + scol];
            float4 cb4 = *(const float4*)&Lt[srow * QPITCH + scol + 4];
            float lv[8] = {ca4.x, ca4.y, ca4.z, ca4.w, cb4.x, cb4.y, cb4.z, cb4.w};
            const float* qr = &QRW[srow * WPITCH + scol + 31 - srow];
            int lim = MMm - t0 + s0 + srow;
#pragma unroll
            for (int j = 0; j < 8; j++) {
                float lvv = lv[j] + qr[j];
                lv[j] = (scol + j <= lim) ? lvv : -1e30f;
            }
            float tmax = lv[0];
#pragma unroll
            for (int j = 1; j < 8; j++) tmax = fmaxf(tmax, lv[j]);
            tmax = fmaxf(tmax, __shfl_xor_sync(0xffffffffu, tmax, 1));
            tmax = fmaxf(tmax, __shfl_xor_sync(0xffffffffu, tmax, 2));
            tmax = fmaxf(tmax, __shfl_xor_sync(0xffffffffu, tmax, 4));
            float m_old = rowm[srow];
            float m_new = fmaxf(m_old, tmax);
            float cfac = __expf(m_old - m_new);
            float p[8], tsum = 0.f;
#pragma unroll
            for (int j = 0; j < 8; j++) {
                p[j] = __expf(lv[j] - m_new);
                tsum += p[j];
            }
            tsum += __shfl_xor_sync(0xffffffffu, tsum, 1);
            tsum += __shfl_xor_sync(0xffffffffu, tsum, 2);
            tsum += __shfl_xor_sync(0xffffffffu, tsum, 4);
            uint4 u0 = make_uint4(f2tf32(p[0]), f2tf32(p[1]), f2tf32(p[2]), f2tf32(p[3]));
            uint4 u1 = make_uint4(f2tf32(p[4]), f2tf32(p[5]), f2tf32(p[6]), f2tf32(p[7]));
            *(uint4*)&Ltb[srow * QPITCH + scol]     = u0;
            *(uint4*)&Ltb[srow * QPITCH + scol + 4] = u1;
            if ((lane & 7) == 0) {
                rowm[srow] = m_new;
                rowsum[srow] = rowsum[srow] * cfac + tsum;
                crow[srow] = cfac;
            }
        }

        CP_WAIT(1);
        __syncthreads();     // sync C

        float c1 = crow[r1], c2 = crow[r2];
#pragma unroll
        for (int nt = 0; nt < 2; nt++) {
            oacc[nt][0] *= c1; oacc[nt][1] *= c1;
            oacc[nt][2] *= c2; oacc[nt][3] *= c2;
        }
#pragma unroll
        for (int k8 = 0; k8 < 64; k8 += 8) {
            uint32_t af[4], bv4[4];
            ldsm_x4(af, lt_a + k8 * 4);
            ldsm_x4(bv4, vt_a + k8 * 4);
            {
                uint32_t bf0[2] = {bv4[0], bv4[1]};
                uint32_t bf1[2] = {bv4[2], bv4[3]};
                mma_tf32(oacc[0], af, bf0);
                mma_tf32(oacc[1], af, bf1);
            }
        }
    }

    __syncthreads();
    float* ozb = (z == 0) ? o0 : (z == 1) ? o1 : (z == 2) ? o2 : o3;
    float* oz = ozb + ((size_t)b * SSq + s0) * DDd + h * DKk;
#pragma unroll
    for (int nt = 0; nt < 2; nt++) {
        int c0 = wn2 + nt * 8 + tg * 2;
        *(float2*)(oz + (size_t)r1 * DDd + c0) = make_float2(oacc[nt][0], oacc[nt][1]);
        *(float2*)(oz + (size_t)r2 * DDd + c0) = make_float2(oacc[nt][2], oacc[nt][3]);
    }
    if (warp < 2 && tg == 0) {
        int zoff = z * (BB * HHh * SSq);
        int base = blockIdx.y * SSq + s0;
        pm[zoff + base + r1] = rowm[r1];
        ps[zoff + base + r1] = rowsum[r1];
        pm[zoff + base + r2] = rowm[r2];
        ps[zoff + base + r2] = rowsum[r2];
    }
}

// ---------------- combine NZ split-attention partials -> attn (tf32 bits) ---
__global__ void attn_combine(const float* __restrict__ o0, const float* __restrict__ o1,
                             const float* __restrict__ o2, const float* __restrict__ o3,
                             const float* __restrict__ pm, const float* __restrict__ ps,
                             float* __restrict__ attn)
{
    int i = blockIdx.x * 256 + threadIdx.x;
    if (i >= (BB * SSq * DDd) / 4) return;
    int e = i * 4;
    int d = e & (DDd - 1);
    int h = d >> 6;
    int s = (e >> 10) & (SSq - 1);
    int b = e >> 19;
    int row = (b * HHh + h) * SSq + s;
    const int Z = BB * HHh * SSq;
    float m0 = pm[row], m1 = pm[Z + row], m2 = pm[2 * Z + row], m3 = pm[3 * Z + row];
    float s0v = ps[row], s1v = ps[Z + row], s2v = ps[2 * Z + row], s3v = ps[3 * Z + row];
    float m = fmaxf(fmaxf(m0, m1), fmaxf(m2, m3));
    float c0 = __expf(m0 - m), c1 = __expf(m1 - m);
    float c2 = __expf(m2 - m), c3 = __expf(m3 - m);
    float inv = 1.f / (c0 * s0v + c1 * s1v + c2 * s2v + c3 * s3v);
    float4 a0 = ((const float4*)o0)[i];
    float4 a1 = ((const float4*)o1)[i];
    float4 a2 = ((const float4*)o2)[i];
    float4 a3 = ((const float4*)o3)[i];
    uint4 u;
    u.x = f2tf32((c0 * a0.x + c1 * a1.x + c2 * a2.x + c3 * a3.x) * inv);
    u.y = f2tf32((c0 * a0.y + c1 * a1.y + c2 * a2.y + c3 * a3.y) * inv);
    u.z = f2tf32((c0 * a0.z + c1 * a1.z + c2 * a2.z + c3 * a3.z) * inv);
    u.w = f2tf32((c0 * a0.w + c1 * a1.w + c2 * a2.w + c3 * a3.w) * inv);
    ((uint4*)attn)[i] = u;
}

// ---------------- residual + LayerNorm over (x0 + x1 + res), dual output ----------------
__global__ void ln_kernel2(const float* __restrict__ x0, const float* __restrict__ x1,
                           const float* __restrict__ res,
                           const float* __restrict__ g, const float* __restrict__ b,
                           float* __restrict__ out, float* __restrict__ outc)
{
    int row = blockIdx.x;
    const float* xr0 = x0 + (size_t)row * DDd;
    const float* xr1 = x1 + (size_t)row * DDd;
    const float* rr  = res + (size_t)row * DDd;
    __shared__ float redA[33], redB[33];
    int tid = threadIdx.x;

    float loc[4];
    float s1 = 0.f, s2 = 0.f;
#pragma unroll
    for (int i = 0; i < 4; i++) {
        int d = tid + i * 256;
        float v = xr0[d] + xr1[d] + rr[d];
        loc[i] = v;
        s1 += v;
        s2 += v * v;
    }
#pragma unroll
    for (int o = 16; o; o >>= 1) {
        s1 += __shfl_xor_sync(0xffffffffu, s1, o);
        s2 += __shfl_xor_sync(0xffffffffu, s2, o);
    }
    if ((tid & 31) == 0) { redA[tid >> 5] = s1; redB[tid >> 5] = s2; }
    __syncthreads();
    if (tid < 32) {
        float a = (tid < 8) ? redA[tid] : 0.f;
        float c = (tid < 8) ? redB[tid] : 0.f;
#pragma unroll
        for (int o = 4; o; o >>= 1) {
            a += __shfl_xor_sync(0xffffffffu, a, o);
            c += __shfl_xor_sync(0xffffffffu, c, o);
        }
        if (tid == 0) { redA[32] = a; redB[32] = c; }
    }
    __syncthreads();
    float mu  = redA[32] * (1.f / DDd);
    float var = redB[32] * (1.f / DDd) - mu * mu;
    float rstd = rsqrtf(var + 1e-5f);
#pragma unroll
    for (int i = 0; i < 4; i++) {
        int d = tid + i * 256;
        float o = (loc[i] - mu) * rstd * g[d] + b[d];
        out[(size_t)row * DDd + d] = o;
        if (outc) outc[(size_t)row * DDd + d] = __uint_as_float(f2tf32(o));
    }
}

// ---------------- host-side orchestration ----------------
extern "C" void kernel_launch(void* const* d_in, const int* in_sizes, int n_in,
                              void* d_out, int out_size)
{
    const float* x      = (const float*)d_in[0];
    const float* memory = (const float*)d_in[1];
    const float* Wq  = (const float*)d_in[2];
    const float* Wk  = (const float*)d_in[3];
    const float* Wv  = (const float*)d_in[4];
    const float* Wr  = (const float*)d_in[5];
    const float* Wo  = (const float*)d_in[6];
    const float* rwb = (const float*)d_in[7];
    const float* rrb = (const float*)d_in[8];
    const float* ln1g = (const float*)d_in[9];
    const float* ln1b = (const float*)d_in[10];
    const float* ln2g = (const float*)d_in[11];
    const float* ln2b = (const float*)d_in[12];
    const float* W1  = (const float*)d_in[13];
    const float* b1  = (const float*)d_in[14];
    const float* W2  = (const float*)d_in[15];
    const float* b2  = (const float*)d_in[16];
    float* out = (float*)d_out;

    float *pos, *q, *kl, *vl, *vtl, *rl, *attn, *tmp, *tmp2, *tmp3, *tmp4, *pm, *ps;
    float *ff, *h, *hc, *h1, *h1c;
    float *wqc, *wkc, *wvc, *wrc, *woc, *w1c, *w2c, *memc, *xc;
    cudaGetSymbolAddress((void**)&pos,  g_pos);
    cudaGetSymbolAddress((void**)&q,    g_q);
    cudaGetSymbolAddress((void**)&kl,   g_kl);
    cudaGetSymbolAddress((void**)&vl,   g_vl);
    cudaGetSymbolAddress((void**)&vtl,  g_vtl);
    cudaGetSymbolAddress((void**)&rl,   g_rl);
    cudaGetSymbolAddress((void**)&attn, g_attn);
    cudaGetSymbolAddress((void**)&tmp,  g_tmp);
    cudaGetSymbolAddress((void**)&tmp2, g_tmp2);
    cudaGetSymbolAddress((void**)&tmp3, g_tmp3);
    cudaGetSymbolAddress((void**)&tmp4, g_tmp4);
    cudaGetSymbolAddress((void**)&pm,   g_pm);
    cudaGetSymbolAddress((void**)&ps,   g_ps);
    cudaGetSymbolAddress((void**)&ff,   g_ff);
    cudaGetSymbolAddress((void**)&h,    g_h);
    cudaGetSymbolAddress((void**)&hc,   g_hc);
    cudaGetSymbolAddress((void**)&h1,   g_h1);
    cudaGetSymbolAddress((void**)&h1c,  g_h1c);
    cudaGetSymbolAddress((void**)&wqc,  g_wqc);
    cudaGetSymbolAddress((void**)&wkc,  g_wkc);
    cudaGetSymbolAddress((void**)&wvc,  g_wvc);
    cudaGetSymbolAddress((void**)&wrc,  g_wrc);
    cudaGetSymbolAddress((void**)&woc,  g_woc);
    cudaGetSymbolAddress((void**)&w1c,  g_w1c);
    cudaGetSymbolAddress((void**)&w2c,  g_w2c);
    cudaGetSymbolAddress((void**)&memc, g_memc);
    cudaGetSymbolAddress((void**)&xc,   g_xc);

    cudaFuncSetAttribute(fused_attn_split, cudaFuncAttributeMaxDynamicSharedMemorySize,
                         SMEM_ATTN_BYTES);

    // single flattened convert launch
    {
        const int nw = (LL * DDd * DDd) / 1024;
        const int nf = (LL * DDd * FFf) / 1024;
        const int nm = (LL * BB * MMm * DDd) / 1024;
        const int nx = (BB * SSq * DDd) / 1024;
        CvtP p;
        const float* ins[9]  = {Wq, Wk, Wv, Wr, Wo, W1, W2, memory, x};
        float*       outs[9] = {wqc, wkc, wvc, wrc, woc, w1c, w2c, memc, xc};
        int          cnts[9] = {nw, nw, nw, nw, nw, nf, nf, nm, nx};
        int acc = 0;
        for (int j = 0; j < 9; j++) {
            p.in[j] = ins[j]; p.out[j] = outs[j];
            p.cum[j] = acc; acc += cnts[j];
        }
        p.cum[9] = acc;
        cvt_all9<<<acc, 256>>>(p);
    }

    pos_kernel<<<(TTt * (DDd / 2) + 255) / 256, 256>>>(pos);

    // upfront static projections (k-mem, v-mem, r for all layers) + static vtrans
    {
        dim3 gS(DDd / 128, LL * 24);    // 768 CTAs
        grouped_static<<<gS, 256>>>(memc, pos, wkc, wvc, wrc, kl, vl, rl);
        dim3 gTS(MMm / 32, DKk / 32, LL * 32);
        vtrans_static<<<gTS, dim3(32, 8)>>>(vl, vtl);
    }

    const float* hcur  = x;
    const float* hcurc = xc;
    for (int l = 0; l < LL; l++) {
        float* klp  = kl  + (size_t)l * BB * TTt * DDd;
        float* vlp  = vl  + (size_t)l * BB * TTt * DDd;
        float* vtlp = vtl + (size_t)l * BB * HHh * DKk * TTt;
        float* rlp  = rl  + (size_t)l * TTt * DDd;

        // per-layer dynamic projections: q, k-h, v-h (192 CTAs)
        dim3 gG(DDd / 128, 24);
        grouped_dyn<<<gG, 256>>>(hcurc,
                                 wqc + (size_t)l * DDd * DDd, wkc + (size_t)l * DDd * DDd,
                                 wvc + (size_t)l * DDd * DDd,
                                 q, klp, vlp);

        // transpose only h-rows of V
        dim3 gT(SSq / 32, DKk / 32, BB * HHh);
        vtrans_dyn<<<gT, dim3(32, 8)>>>(vlp, vtlp);

        // split-T flash attention
        dim3 gA(SSq / SMT, BB * HHh, NZ);
        fused_attn_split<<<gA, 256, SMEM_ATTN_BYTES>>>(
            q, klp, vtlp, rlp, rwb + (size_t)l * HHh * DKk, rrb + (size_t)l * HHh * DKk,
            tmp, tmp2, tmp3, tmp4, pm, ps);
        attn_combine<<<(BB * SSq * DDd / 4 + 255) / 256, 256>>>(
            tmp, tmp2, tmp3, tmp4, pm, ps, attn);

        dim3 gO(DDd / 128, (BB * SSq) / 64, 2);
        tc_gemm_splitk<64, 4><<<gO, 256>>>(attn, woc + (size_t)l * DDd * DDd,
                                           tmp, tmp2, DDd, DDd, nullptr);
        ln_kernel2<<<BB * SSq, 256>>>(tmp, tmp2, hcur,
                                      ln1g + l * DDd, ln1b + l * DDd, h1, h1c);

        dim3 gF1(FFf / 128, (BB * SSq) / 128);
        tc_gemm_k<128, 4><<<gF1, 256>>>(h1c, w1c + (size_t)l * DDd * FFf, ff,
                                        FFf, DDd, 1.f, b1 + l * FFf, 1, 1);
        dim3 gF2(DDd / 128, (BB * SSq) / 64, 2);
        tc_gemm_splitk<64, 4><<<gF2, 256>>>(ff, w2c + (size_t)l * FFf * DDd,
                                            tmp, tmp2, DDd, FFf, b2 + l * DDd);

        if (l == LL - 1) {
            ln_kernel2<<<BB * SSq, 256>>>(tmp, tmp2, h1,
                                          ln2g + l * DDd, ln2b + l * DDd, out, nullptr);
        } else {
            ln_kernel2<<<BB * SSq, 256>>>(tmp, tmp2, h1,
                                          ln2g + l * DDd, ln2b + l * DDd, h, hc);
            hcur = h;
            hcurc = hc;
        }
    }
}

// round 17
// speedup vs baseline: 1.0431x; 1.0431x over previous
#include <cuda_runtime.h>
#include <math.h>
#include <stdint.h>

// Problem dims
#define LL  4
#define BB  2
#define SSq 512
#define MMm 512
#define DDd 1024
#define HHh 16
#define DKk 64
#define FFf 4096
#define TTt (SSq + MMm)   // 1024
#define NZ  4             // attention T-split factor

// ---------------- scratch ----------------
__device__ float g_pos[TTt * DDd];        // tf32 bits
__device__ float g_q  [BB * SSq * DDd];   // fp32
__device__ float g_k  [BB * TTt * DDd];   // tf32 bits
__device__ float g_vt [BB * HHh * DKk * TTt]; // tf32 bits [b][h][dk][t]
__device__ float g_r  [TTt * DDd];        // tf32 bits
__device__ float g_attn[BB * SSq * DDd];  // tf32 bits
__device__ float g_tmp [BB * SSq * DDd];
__device__ float g_tmp2[BB * SSq * DDd];
__device__ float g_tmp3[BB * SSq * DDd];
__device__ float g_tmp4[BB * SSq * DDd];
__device__ float g_pm [NZ * BB * HHh * SSq];
__device__ float g_ps [NZ * BB * HHh * SSq];
__device__ float g_ff  [BB * SSq * FFf];  // tf32 bits
__device__ float g_h   [BB * SSq * DDd];  // fp32 residual
__device__ float g_hc  [BB * SSq * DDd];  // tf32 copy
__device__ float g_h1  [BB * SSq * DDd];  // fp32 residual
__device__ float g_h1c [BB * SSq * DDd];  // tf32 copy
// pre-converted operands (tf32 bits)
__device__ float g_wqc[LL * DDd * DDd];
__device__ float g_wkc[LL * DDd * DDd];
__device__ float g_wvc[LL * DDd * DDd];
__device__ float g_wrc[LL * DDd * DDd];
__device__ float g_woc[LL * DDd * DDd];
__device__ float g_w1c[LL * DDd * FFf];
__device__ float g_w2c[LL * FFf * DDd];
__device__ float g_memc[LL * BB * MMm * DDd];
__device__ float g_xc  [BB * SSq * DDd];

// ---------------- PTX helpers ----------------
__device__ __forceinline__ uint32_t f2tf32(float f) {
    uint32_t u;
    asm("cvt.rna.tf32.f32 %0, %1;" : "=r"(u) : "f"(f));
    return u;
}
__device__ __forceinline__ void mma_tf32(float c[4], const uint32_t a[4], const uint32_t b[2]) {
    asm volatile(
        "mma.sync.aligned.m16n8k8.row.col.f32.tf32.tf32.f32 "
        "{%0,%1,%2,%3},{%4,%5,%6,%7},{%8,%9},{%0,%1,%2,%3};"
        : "+f"(c[0]), "+f"(c[1]), "+f"(c[2]), "+f"(c[3])
        : "r"(a[0]), "r"(a[1]), "r"(a[2]), "r"(a[3]), "r"(b[0]), "r"(b[1]));
}
__device__ __forceinline__ void cp_async16(void* smem, const void* g) {
    uint32_t s = (uint32_t)__cvta_generic_to_shared(smem);
    asm volatile("cp.async.cg.shared.global [%0], [%1], 16;" :: "r"(s), "l"(g));
}
#define CP_COMMIT() asm volatile("cp.async.commit_group;")
#define CP_WAIT(n)  asm volatile("cp.async.wait_group %0;" :: "n"(n))

__device__ __forceinline__ uint32_t sm_u32(const void* p) {
    return (uint32_t)__cvta_generic_to_shared(p);
}
__device__ __forceinline__ void ldsm_x4(uint32_t r[4], uint32_t addr) {
    asm volatile("ldmatrix.sync.aligned.m8n8.x4.shared.b16 {%0,%1,%2,%3}, [%4];"
                 : "=r"(r[0]), "=r"(r[1]), "=r"(r[2]), "=r"(r[3]) : "r"(addr));
}
__device__ __forceinline__ void ldsm_x2(uint32_t r[2], uint32_t addr) {
    asm volatile("ldmatrix.sync.aligned.m8n8.x2.shared.b16 {%0,%1}, [%2];"
                 : "=r"(r[0]), "=r"(r[1]) : "r"(addr));
}

// ---------------- flattened 9-region fp32 -> tf32-bit convert ----------------
struct CvtP {
    const float* in[9];
    float* out[9];
    int cum[10];
};
__global__ void cvt_all9(CvtP p)
{
    int blk = blockIdx.x;
    int r = 0;
#pragma unroll
    for (int j = 1; j < 9; j++) r += (blk >= p.cum[j]);
    int i = (blk - p.cum[r]) * 256 + threadIdx.x;
    float4 v = ((const float4*)p.in[r])[i];
    uint4 u = make_uint4(f2tf32(v.x), f2tf32(v.y), f2tf32(v.z), f2tf32(v.w));
    ((uint4*)p.out[r])[i] = u;
}

// ---------------- positional encodings (tf32 out) ----------------
__global__ void pos_kernel(float* __restrict__ pos)
{
    int idx = blockIdx.x * blockDim.x + threadIdx.x;
    if (idx >= TTt * (DDd / 2)) return;
    int t = idx / (DDd / 2), j = idx % (DDd / 2);
    double invf = exp(((double)(-2 * j) / (double)DDd) * 9.210340371976184);
    double ang  = (double)(TTt - 1 - t) * invf;
    double kk   = floor(ang * 0.15915494309189535);
    float a = (float)(ang - kk * 6.283185307179586);
    pos[(size_t)t * DDd + j]           = __uint_as_float(f2tf32(sinf(a)));
    pos[(size_t)t * DDd + j + DDd / 2] = __uint_as_float(f2tf32(cosf(a)));
}

// ======================================================================
// Async GEMM core: pre-converted tf32 operands. tmode!=0 => transposed
// epilogue: Cg[(size_t)col*TTt + row] (for direct V^T emission).
// ======================================================================
template<int BM, int NWN>
__device__ __forceinline__ void gemm_core_async(
    const float* __restrict__ Ag, const float* __restrict__ Bg, float* __restrict__ Cg,
    int N, int K, int lda, float alpha, const float* __restrict__ biasg, int relu,
    int cvt_out, int tmode)
{
    constexpr int BN = NWN * 32;
    constexpr int NWM = 8 / NWN;
    constexpr int WM = BM / NWM;
    constexpr int MT = WM / 16;
    constexpr int BPITCH = BN + 8;
    constexpr int NA_CH = BM / 64;
    constexpr int NB_CH = BN / 64;

    __shared__ uint32_t As[2][BM][20];
    __shared__ uint32_t Bs[2][16][BPITCH];

    int tid = threadIdx.x, lane = tid & 31, warp = tid >> 5;
    int g = lane >> 2, tg = lane & 3;
    int warp_m = warp % NWM, warp_n = warp / NWM;
    int wm = warp_m * WM, wn = warp_n * 32;

    float acc[MT][4][4];
#pragma unroll
    for (int mt = 0; mt < MT; mt++)
#pragma unroll
        for (int nt = 0; nt < 4; nt++)
#pragma unroll
            for (int i = 0; i < 4; i++) acc[mt][nt][i] = 0.f;

    int ar[NA_CH], ak[NA_CH];
#pragma unroll
    for (int j = 0; j < NA_CH; j++) {
        int c = tid + j * 256;
        ar[j] = c >> 2; ak[j] = (c & 3) * 4;
    }
    int bk[NB_CH], bn[NB_CH];
#pragma unroll
    for (int j = 0; j < NB_CH; j++) {
        int c = tid + j * 256;
        if (BN == 128) { bk[j] = c >> 5; bn[j] = (c & 31) * 4; }
        else           { bk[j] = c >> 4; bn[j] = (c & 15) * 4; }
    }

    int nk = K / 16;

#pragma unroll
    for (int j = 0; j < NA_CH; j++)
        cp_async16(&As[0][ar[j]][ak[j]], Ag + (size_t)ar[j] * lda + ak[j]);
#pragma unroll
    for (int j = 0; j < NB_CH; j++)
        cp_async16(&Bs[0][bk[j]][bn[j]], Bg + (size_t)bk[j] * N + bn[j]);
    CP_COMMIT();

    for (int kt = 0; kt < nk; kt++) {
        int buf = kt & 1;
        bool more = (kt + 1 < nk);
        if (more) {
            int nb = buf ^ 1;
#pragma unroll
            for (int j = 0; j < NA_CH; j++)
                cp_async16(&As[nb][ar[j]][ak[j]],
                           Ag + (size_t)ar[j] * lda + (kt + 1) * 16 + ak[j]);
#pragma unroll
            for (int j = 0; j < NB_CH; j++)
                cp_async16(&Bs[nb][bk[j]][bn[j]],
                           Bg + (size_t)((kt + 1) * 16 + bk[j]) * N + bn[j]);
            CP_COMMIT();
            CP_WAIT(1);
        } else {
            CP_WAIT(0);
        }
        __syncthreads();

#pragma unroll
        for (int ks = 0; ks < 2; ks++) {
            uint32_t af[MT][4], bf[4][2];
#pragma unroll
            for (int mt = 0; mt < MT; mt++) {
                int row = wm + mt * 16;
                af[mt][0] = As[buf][row + g][ks * 8 + tg];
                af[mt][1] = As[buf][row + g + 8][ks * 8 + tg];
                af[mt][2] = As[buf][row + g][ks * 8 + tg + 4];
                af[mt][3] = As[buf][row + g + 8][ks * 8 + tg + 4];
            }
#pragma unroll
            for (int nt = 0; nt < 4; nt++) {
                int col = wn + nt * 8 + g;
                bf[nt][0] = Bs[buf][ks * 8 + tg][col];
                bf[nt][1] = Bs[buf][ks * 8 + tg + 4][col];
            }
#pragma unroll
            for (int mt = 0; mt < MT; mt++)
#pragma unroll
                for (int nt = 0; nt < 4; nt++) mma_tf32(acc[mt][nt], af[mt], bf[nt]);
        }
        if (more) __syncthreads();
    }

#pragma unroll
    for (int mt = 0; mt < MT; mt++) {
#pragma unroll
        for (int nt = 0; nt < 4; nt++) {
            int row = wm + mt * 16 + g;
            int col = wn + nt * 8 + tg * 2;
            float bx0 = 0.f, bx1 = 0.f;
            if (biasg) { bx0 = biasg[col]; bx1 = biasg[col + 1]; }
            float v0 = acc[mt][nt][0] * alpha + bx0;
            float v1 = acc[mt][nt][1] * alpha + bx1;
            float v2 = acc[mt][nt][2] * alpha + bx0;
            float v3 = acc[mt][nt][3] * alpha + bx1;
            if (relu) {
                v0 = fmaxf(v0, 0.f); v1 = fmaxf(v1, 0.f);
                v2 = fmaxf(v2, 0.f); v3 = fmaxf(v3, 0.f);
            }
            if (cvt_out) {
                v0 = __uint_as_float(f2tf32(v0));
                v1 = __uint_as_float(f2tf32(v1));
                v2 = __uint_as_float(f2tf32(v2));
                v3 = __uint_as_float(f2tf32(v3));
            }
            if (tmode) {
                // transposed: Cg[(col)*TTt + row]
                Cg[(size_t)col * TTt + row]           = v0;
                Cg[(size_t)(col + 1) * TTt + row]     = v1;
                Cg[(size_t)col * TTt + row + 8]       = v2;
                Cg[(size_t)(col + 1) * TTt + row + 8] = v3;
            } else {
                *(float2*)(Cg + (size_t)row * N + col)       = make_float2(v0, v1);
                *(float2*)(Cg + (size_t)(row + 8) * N + col) = make_float2(v2, v3);
            }
        }
    }
}

template<int BM, int NWN>
__global__ void __launch_bounds__(256) tc_gemm_k(
    const float* __restrict__ A, const float* __restrict__ B, float* __restrict__ C,
    int N, int K, float alpha, const float* __restrict__ bias, int relu, int cvt_out)
{
    constexpr int BN = NWN * 32;
    const float* Ag = A + (size_t)blockIdx.y * BM * K;
    const float* Bg = B + (size_t)blockIdx.x * BN;
    float* Cg = C + (size_t)blockIdx.y * BM * N + (size_t)blockIdx.x * BN;
    const float* bg = bias ? bias + (size_t)blockIdx.x * BN : nullptr;
    gemm_core_async<BM, NWN>(Ag, Bg, Cg, N, K, K, alpha, bg, relu, cvt_out, 0);
}

template<int BM, int NWN>
__global__ void __launch_bounds__(256) tc_gemm_splitk(
    const float* __restrict__ A, const float* __restrict__ B,
    float* __restrict__ C0, float* __restrict__ C1,
    int N, int K, const float* __restrict__ bias)
{
    constexpr int BN = NWN * 32;
    int z = blockIdx.z;
    int K2 = K >> 1;
    const float* Ag = A + (size_t)blockIdx.y * BM * K + (size_t)z * K2;
    const float* Bg = B + (size_t)z * K2 * N + (size_t)blockIdx.x * BN;
    float* C = z ? C1 : C0;
    float* Cg = C + (size_t)blockIdx.y * BM * N + (size_t)blockIdx.x * BN;
    const float* bg = (bias && z == 0) ? bias + (size_t)blockIdx.x * BN : nullptr;
    gemm_core_async<BM, NWN>(Ag, Bg, Cg, N, K2, K, 1.f, bg, 0, 0, 0);
}

// grouped q/k/v/r projections (R14 structure). V blocks emit transposed
// directly into vt[b][h][dk][t].
__global__ void __launch_bounds__(256) grouped_qkvr(
    const float* __restrict__ hcc, const float* __restrict__ memc, const float* __restrict__ pos,
    const float* __restrict__ Wq, const float* __restrict__ Wk,
    const float* __restrict__ Wv, const float* __restrict__ Wr,
    float* __restrict__ q, float* __restrict__ k, float* __restrict__ vt, float* __restrict__ r)
{
    int y = blockIdx.y;
    const float* Ag; const float* B; float* Cg; float alpha = 1.f; int cvt = 1; int tmode = 0;
    if (y < 8) {
        Ag = hcc + (size_t)y * 128 * DDd; B = Wq;
        Cg = q + (size_t)y * 128 * DDd + (size_t)blockIdx.x * 128;
        alpha = 0.125f; cvt = 0;
    } else if (y < 40) {
        int yy = (y < 24) ? y - 8 : y - 24;
        int row0 = yy * 128;
        int b = row0 >> 10, t0 = row0 & 1023;
        Ag = (t0 < MMm) ? memc + ((size_t)b * MMm + t0) * DDd
                        : hcc  + ((size_t)b * SSq + (t0 - MMm)) * DDd;
        if (y < 24) {
            B = Wk;
            Cg = k + (size_t)yy * 128 * DDd + (size_t)blockIdx.x * 128;
        } else {
            B = Wv;
            // transposed output: vt + (b*1024 + gcol0)*TTt + t0
            Cg = vt + ((size_t)b * HHh * DKk + (size_t)blockIdx.x * 128) * TTt + t0;
            tmode = 1;
        }
    } else {
        int yy = y - 40;
        Ag = pos + (size_t)yy * 128 * DDd; B = Wr;
        Cg = r + (size_t)yy * 128 * DDd + (size_t)blockIdx.x * 128;
    }
    const float* Bg = B + (size_t)blockIdx.x * 128;
    gemm_core_async<128, 4>(Ag, Bg, Cg, DDd, DDd, DDd, alpha, nullptr, 0, cvt, tmode);
}

// ======================================================================
// Flash fused attention, split over T into NZ partitions (R14 verified).
// ======================================================================
#define SMT   32
#define TN    64
#define QPITCH 68
#define WPITCH 100
#define SMEM_ATTN_FLOATS (2*SMT*QPITCH + 64*QPITCH + 96*QPITCH + 64*QPITCH + SMT*QPITCH + SMT*WPITCH + 96)
#define SMEM_ATTN_BYTES  (SMEM_ATTN_FLOATS * 4)

__global__ void __launch_bounds__(256) fused_attn_split(
    const float* __restrict__ q, const float* __restrict__ k, const float* __restrict__ vt,
    const float* __restrict__ r, const float* __restrict__ rwb, const float* __restrict__ rrb,
    float* __restrict__ o0, float* __restrict__ o1,
    float* __restrict__ o2, float* __restrict__ o3,
    float* __restrict__ pm, float* __restrict__ ps)
{
    extern __shared__ float sm[];
    uint32_t* Qcb  = (uint32_t*)sm;
    uint32_t* Qrb  = Qcb + SMT * QPITCH;
    uint32_t* Ktb  = Qrb + SMT * QPITCH;
    uint32_t* Rwb  = Ktb + 64 * QPITCH;
    uint32_t* Vtb  = Rwb + 96 * QPITCH;   // [64 dk][68 t]
    float*    Lt   = (float*)(Vtb + 64 * QPITCH);
    float*    QRW  = Lt + SMT * QPITCH;
    float*    crow = QRW + SMT * WPITCH;
    float*    rowm = crow + 32;
    float*    rowsum = rowm + 32;
    uint32_t* Ltb  = (uint32_t*)Lt;

    int tid = threadIdx.x, lane = tid & 31, warp = tid >> 5;
    int g = lane >> 2, tg = lane & 3;
    int s0 = (15 - blockIdx.x) * SMT;
    int b = blockIdx.y >> 4, h = blockIdx.y & 15;
    int z = blockIdx.z;

    const float* qb = q + (size_t)b * SSq * DDd + h * DKk;
    const float* kb = k + (size_t)b * TTt * DDd + h * DKk;
    const float* vtb = vt + (size_t)(b * HHh + h) * DKk * TTt;
    const float* rb = r + h * DKk;
    const float* wbv = rwb + h * DKk;
    const float* rbv = rrb + h * DKk;

    int ntiles = (s0 + 543) / 64 + 1;
    int tbeg = (z * ntiles) / NZ;
    int tend = ((z + 1) * ntiles) / NZ;

    int lrow = tid >> 4, lk0 = (tid & 15) * 4;

    auto issue_KR = [&](int it) {
        if (it < tend) {
            int t0 = it * TN, jb = t0 - s0 + 480;
#pragma unroll
            for (int j = 0; j < 4; j++) {
                int row = lrow + j * 16;
                cp_async16(&Ktb[row * QPITCH + lk0], kb + (size_t)(t0 + row) * DDd + lk0);
            }
#pragma unroll
            for (int j = 0; j < 6; j++) {
                int row = lrow + j * 16;
                int jg = jb + row;
                if (jg > TTt - 1) jg = TTt - 1;
                if (jg < 0) jg = 0;
                cp_async16(&Rwb[row * QPITCH + lk0], rb + (size_t)jg * DDd + lk0);
            }
        }
        CP_COMMIT();
    };
    auto issue_V = [&](int it) {
        if (it < tend) {
            int t0 = it * TN;
#pragma unroll
            for (int j = 0; j < 4; j++) {
                int row = lrow + j * 16;
                cp_async16(&Vtb[row * QPITCH + lk0], vtb + (size_t)row * TTt + t0 + lk0);
            }
        }
        CP_COMMIT();
    };

    issue_KR(tbeg);

#pragma unroll
    for (int j = 0; j < 2; j++) {
        int c = tid + j * 256;
        int row = c >> 4, k0 = (c & 15) * 4;
        float4 qv = *(const float4*)(qb + (size_t)(s0 + row) * DDd + k0);
        float4 w4 = *(const float4*)(wbv + k0);
        float4 r4 = *(const float4*)(rbv + k0);
        Qcb[row * QPITCH + k0 + 0] = f2tf32(qv.x + w4.x);
        Qcb[row * QPITCH + k0 + 1] = f2tf32(qv.y + w4.y);
        Qcb[row * QPITCH + k0 + 2] = f2tf32(qv.z + w4.z);
        Qcb[row * QPITCH + k0 + 3] = f2tf32(qv.w + w4.w);
        Qrb[row * QPITCH + k0 + 0] = f2tf32(qv.x + r4.x);
        Qrb[row * QPITCH + k0 + 1] = f2tf32(qv.y + r4.y);
        Qrb[row * QPITCH + k0 + 2] = f2tf32(qv.z + r4.z);
        Qrb[row * QPITCH + k0 + 3] = f2tf32(qv.w + r4.w);
    }
    if (tid < 32) { rowm[tid] = -1e30f; rowsum[tid] = 0.f; }

    int wm2 = (warp & 1) * 16;
    int wn2 = (warp >> 1) * 16;
    int wn3 = (warp >> 1) * 24;
    int r1 = wm2 + g, r2 = r1 + 8;

    int srow = warp * 4 + (lane >> 3);
    int scol = (lane & 7) * 8;

    int a_row = (lane & 7) + ((lane >> 3) & 1) * 8;
    int a_col = (lane >> 4) * 4;
    int b_row = (lane & 7) + ((lane >> 4) & 1) * 8;
    int b_col = ((lane >> 3) & 1) * 4;
    int c_row = lane & 7;
    int c_col = ((lane >> 3) & 1) * 4;

    uint32_t qc_a  = sm_u32(&Qcb[(wm2 + a_row) * QPITCH + a_col]);
    uint32_t qr_a  = sm_u32(&Qrb[(wm2 + a_row) * QPITCH + a_col]);
    uint32_t lt_a  = sm_u32(&Ltb[(wm2 + a_row) * QPITCH + a_col]);
    uint32_t kt_a  = sm_u32(&Ktb[(wn2 + b_row) * QPITCH + b_col]);
    uint32_t vt_a  = sm_u32(&Vtb[(wn2 + b_row) * QPITCH + b_col]);
    uint32_t rw4_a = sm_u32(&Rwb[(wn3 + b_row) * QPITCH + b_col]);
    uint32_t rw2_a = sm_u32(&Rwb[(wn3 + 16 + c_row) * QPITCH + c_col]);

    float oacc[2][4];
#pragma unroll
    for (int nt = 0; nt < 2; nt++)
#pragma unroll
        for (int i = 0; i < 4; i++) oacc[nt][i] = 0.f;

    for (int it = tbeg; it < tend; it++) {
        int t0 = it * TN;
        CP_WAIT(0);
        __syncthreads();     // sync A

        issue_V(it);

        float ca[2][4], ra[3][4];
#pragma unroll
        for (int nt = 0; nt < 2; nt++)
#pragma unroll
            for (int i = 0; i < 4; i++) ca[nt][i] = 0.f;
#pragma unroll
        for (int nt = 0; nt < 3; nt++)
#pragma unroll
            for (int i = 0; i < 4; i++) ra[nt][i] = 0.f;

#pragma unroll
        for (int k8 = 0; k8 < 64; k8 += 8) {
            uint32_t koff = k8 * 4;
            uint32_t af[4], afr[4], bk4[4], br4[4], br2[2];
            ldsm_x4(af,  qc_a + koff);
            ldsm_x4(afr, qr_a + koff);
            ldsm_x4(bk4, kt_a + koff);
            ldsm_x4(br4, rw4_a + koff);
            ldsm_x2(br2, rw2_a + koff);
            {
                uint32_t bf0[2] = {bk4[0], bk4[1]};
                uint32_t bf1[2] = {bk4[2], bk4[3]};
                mma_tf32(ca[0], af, bf0);
                mma_tf32(ca[1], af, bf1);
            }
            {
                uint32_t bf0[2] = {br4[0], br4[1]};
                uint32_t bf1[2] = {br4[2], br4[3]};
                mma_tf32(ra[0], afr, bf0);
                mma_tf32(ra[1], afr, bf1);
                mma_tf32(ra[2], afr, br2);
            }
        }
#pragma unroll
        for (int nt = 0; nt < 2; nt++) {
            int c0 = wn2 + nt * 8 + tg * 2;
            Lt[r1 * QPITCH + c0]     = ca[nt][0];
            Lt[r1 * QPITCH + c0 + 1] = ca[nt][1];
            Lt[r2 * QPITCH + c0]     = ca[nt][2];
            Lt[r2 * QPITCH + c0 + 1] = ca[nt][3];
        }
#pragma unroll
        for (int nt = 0; nt < 3; nt++) {
            int c0 = wn3 + nt * 8 + tg * 2;
            QRW[r1 * WPITCH + c0]     = ra[nt][0];
            QRW[r1 * WPITCH + c0 + 1] = ra[nt][1];
            QRW[r2 * WPITCH + c0]     = ra[nt][2];
            QRW[r2 * WPITCH + c0 + 1] = ra[nt][3];
        }
        __syncthreads();     // sync B

        issue_KR(it + 1);

        // warp-exclusive row softmax
        {
            float4 ca4 = *(const float4*)&Lt[srow * QPITCH + scol];
            float4 cb4 = *(const float4*)&Lt[srow * QPITCH + scol + 4];
            float lv[8] = {ca4.x, ca4.y, ca4.z, ca4.w, cb4.x, cb4.y, cb4.z, cb4.w};
            const float* qr = &QRW[srow * WPITCH + scol + 31 - srow];
            int lim = MMm - t0 + s0 + srow;
#pragma unroll
            for (int j = 0; j < 8; j++) {
                float lvv = lv[j] + qr[j];
                lv[j] = (scol + j <= lim) ? lvv : -1e30f;
            }
            float tmax = lv[0];
#pragma unroll
            for (int j = 1; j < 8; j++) tmax = fmaxf(tmax, lv[j]);
            tmax = fmaxf(tmax, __shfl_xor_sync(0xffffffffu, tmax, 1));
            tmax = fmaxf(tmax, __shfl_xor_sync(0xffffffffu, tmax, 2));
            tmax = fmaxf(tmax, __shfl_xor_sync(0xffffffffu, tmax, 4));
            float m_old = rowm[srow];
            float m_new = fmaxf(m_old, tmax);
            float cfac = __expf(m_old - m_new);
            float p[8], tsum = 0.f;
#pragma unroll
            for (int j = 0; j < 8; j++) {
                p[j] = __expf(lv[j] - m_new);
                tsum += p[j];
            }
            tsum += __shfl_xor_sync(0xffffffffu, tsum, 1);
            tsum += __shfl_xor_sync(0xffffffffu, tsum, 2);
            tsum += __shfl_xor_sync(0xffffffffu, tsum, 4);
            uint4 u0 = make_uint4(f2tf32(p[0]), f2tf32(p[1]), f2tf32(p[2]), f2tf32(p[3]));
            uint4 u1 = make_uint4(f2tf32(p[4]), f2tf32(p[5]), f2tf32(p[6]), f2tf32(p[7]));
            *(uint4*)&Ltb[srow * QPITCH + scol]     = u0;
            *(uint4*)&Ltb[srow * QPITCH + scol + 4] = u1;
            if ((lane & 7) == 0) {
                rowm[srow] = m_new;
                rowsum[srow] = rowsum[srow] * cfac + tsum;
                crow[srow] = cfac;
            }
        }

        CP_WAIT(1);
        __syncthreads();     // sync C

        float c1 = crow[r1], c2 = crow[r2];
#pragma unroll
        for (int nt = 0; nt < 2; nt++) {
            oacc[nt][0] *= c1; oacc[nt][1] *= c1;
            oacc[nt][2] *= c2; oacc[nt][3] *= c2;
        }
#pragma unroll
        for (int k8 = 0; k8 < 64; k8 += 8) {
            uint32_t af[4], bv4[4];
            ldsm_x4(af, lt_a + k8 * 4);
            ldsm_x4(bv4, vt_a + k8 * 4);
            {
                uint32_t bf0[2] = {bv4[0], bv4[1]};
                uint32_t bf1[2] = {bv4[2], bv4[3]};
                mma_tf32(oacc[0], af, bf0);
                mma_tf32(oacc[1], af, bf1);
            }
        }
    }

    __syncthreads();
    float* ozb = (z == 0) ? o0 : (z == 1) ? o1 : (z == 2) ? o2 : o3;
    float* oz = ozb + ((size_t)b * SSq + s0) * DDd + h * DKk;
#pragma unroll
    for (int nt = 0; nt < 2; nt++) {
        int c0 = wn2 + nt * 8 + tg * 2;
        *(float2*)(oz + (size_t)r1 * DDd + c0) = make_float2(oacc[nt][0], oacc[nt][1]);
        *(float2*)(oz + (size_t)r2 * DDd + c0) = make_float2(oacc[nt][2], oacc[nt][3]);
    }
    if (warp < 2 && tg == 0) {
        int zoff = z * (BB * HHh * SSq);
        int base = blockIdx.y * SSq + s0;
        pm[zoff + base + r1] = rowm[r1];
        ps[zoff + base + r1] = rowsum[r1];
        pm[zoff + base + r2] = rowm[r2];
        ps[zoff + base + r2] = rowsum[r2];
    }
}

// ---------------- combine NZ split-attention partials -> attn (tf32 bits) ---
__global__ void attn_combine(const float* __restrict__ o0, const float* __restrict__ o1,
                             const float* __restrict__ o2, const float* __restrict__ o3,
                             const float* __restrict__ pm, const float* __restrict__ ps,
                             float* __restrict__ attn)
{
    int i = blockIdx.x * 256 + threadIdx.x;
    if (i >= (BB * SSq * DDd) / 4) return;
    int e = i * 4;
    int d = e & (DDd - 1);
    int h = d >> 6;
    int s = (e >> 10) & (SSq - 1);
    int b = e >> 19;
    int row = (b * HHh + h) * SSq + s;
    const int Z = BB * HHh * SSq;
    float m0 = pm[row], m1 = pm[Z + row], m2 = pm[2 * Z + row], m3 = pm[3 * Z + row];
    float s0v = ps[row], s1v = ps[Z + row], s2v = ps[2 * Z + row], s3v = ps[3 * Z + row];
    float m = fmaxf(fmaxf(m0, m1), fmaxf(m2, m3));
    float c0 = __expf(m0 - m), c1 = __expf(m1 - m);
    float c2 = __expf(m2 - m), c3 = __expf(m3 - m);
    float inv = 1.f / (c0 * s0v + c1 * s1v + c2 * s2v + c3 * s3v);
    float4 a0 = ((const float4*)o0)[i];
    float4 a1 = ((const float4*)o1)[i];
    float4 a2 = ((const float4*)o2)[i];
    float4 a3 = ((const float4*)o3)[i];
    uint4 u;
    u.x = f2tf32((c0 * a0.x + c1 * a1.x + c2 * a2.x + c3 * a3.x) * inv);
    u.y = f2tf32((c0 * a0.y + c1 * a1.y + c2 * a2.y + c3 * a3.y) * inv);
    u.z = f2tf32((c0 * a0.z + c1 * a1.z + c2 * a2.z + c3 * a3.z) * inv);
    u.w = f2tf32((c0 * a0.w + c1 * a1.w + c2 * a2.w + c3 * a3.w) * inv);
    ((uint4*)attn)[i] = u;
}

// ---------------- residual + LayerNorm over (x0 + x1 + res), dual output ----------------
__global__ void ln_kernel2(const float* __restrict__ x0, const float* __restrict__ x1,
                           const float* __restrict__ res,
                           const float* __restrict__ g, const float* __restrict__ b,
                           float* __restrict__ out, float* __restrict__ outc)
{
    int row = blockIdx.x;
    const float* xr0 = x0 + (size_t)row * DDd;
    const float* xr1 = x1 + (size_t)row * DDd;
    const float* rr  = res + (size_t)row * DDd;
    __shared__ float redA[33], redB[33];
    int tid = threadIdx.x;

    float loc[4];
    float s1 = 0.f, s2 = 0.f;
#pragma unroll
    for (int i = 0; i < 4; i++) {
        int d = tid + i * 256;
        float v = xr0[d] + xr1[d] + rr[d];
        loc[i] = v;
        s1 += v;
        s2 += v * v;
    }
#pragma unroll
    for (int o = 16; o; o >>= 1) {
        s1 += __shfl_xor_sync(0xffffffffu, s1, o);
        s2 += __shfl_xor_sync(0xffffffffu, s2, o);
    }
    if ((tid & 31) == 0) { redA[tid >> 5] = s1; redB[tid >> 5] = s2; }
    __syncthreads();
    if (tid < 32) {
        float a = (tid < 8) ? redA[tid] : 0.f;
        float c = (tid < 8) ? redB[tid] : 0.f;
#pragma unroll
        for (int o = 4; o; o >>= 1) {
            a += __shfl_xor_sync(0xffffffffu, a, o);
            c += __shfl_xor_sync(0xffffffffu, c, o);
        }
        if (tid == 0) { redA[32] = a; redB[32] = c; }
    }
    __syncthreads();
    float mu  = redA[32] * (1.f / DDd);
    float var = redB[32] * (1.f / DDd) - mu * mu;
    float rstd = rsqrtf(var + 1e-5f);
#pragma unroll
    for (int i = 0; i < 4; i++) {
        int d = tid + i * 256;
        float o = (loc[i] - mu) * rstd * g[d] + b[d];
        out[(size_t)row * DDd + d] = o;
        if (outc) outc[(size_t)row * DDd + d] = __uint_as_float(f2tf32(o));
    }
}

// ---------------- host-side orchestration ----------------
extern "C" void kernel_launch(void* const* d_in, const int* in_sizes, int n_in,
                              void* d_out, int out_size)
{
    const float* x      = (const float*)d_in[0];
    const float* memory = (const float*)d_in[1];
    const float* Wq  = (const float*)d_in[2];
    const float* Wk  = (const float*)d_in[3];
    const float* Wv  = (const float*)d_in[4];
    const float* Wr  = (const float*)d_in[5];
    const float* Wo  = (const float*)d_in[6];
    const float* rwb = (const float*)d_in[7];
    const float* rrb = (const float*)d_in[8];
    const float* ln1g = (const float*)d_in[9];
    const float* ln1b = (const float*)d_in[10];
    const float* ln2g = (const float*)d_in[11];
    const float* ln2b = (const float*)d_in[12];
    const float* W1  = (const float*)d_in[13];
    const float* b1  = (const float*)d_in[14];
    const float* W2  = (const float*)d_in[15];
    const float* b2  = (const float*)d_in[16];
    float* out = (float*)d_out;

    float *pos, *q, *k, *vt, *r, *attn, *tmp, *tmp2, *tmp3, *tmp4, *pm, *ps;
    float *ff, *h, *hc, *h1, *h1c;
    float *wqc, *wkc, *wvc, *wrc, *woc, *w1c, *w2c, *memc, *xc;
    cudaGetSymbolAddress((void**)&pos,  g_pos);
    cudaGetSymbolAddress((void**)&q,    g_q);
    cudaGetSymbolAddress((void**)&k,    g_k);
    cudaGetSymbolAddress((void**)&vt,   g_vt);
    cudaGetSymbolAddress((void**)&r,    g_r);
    cudaGetSymbolAddress((void**)&attn, g_attn);
    cudaGetSymbolAddress((void**)&tmp,  g_tmp);
    cudaGetSymbolAddress((void**)&tmp2, g_tmp2);
    cudaGetSymbolAddress((void**)&tmp3, g_tmp3);
    cudaGetSymbolAddress((void**)&tmp4, g_tmp4);
    cudaGetSymbolAddress((void**)&pm,   g_pm);
    cudaGetSymbolAddress((void**)&ps,   g_ps);
    cudaGetSymbolAddress((void**)&ff,   g_ff);
    cudaGetSymbolAddress((void**)&h,    g_h);
    cudaGetSymbolAddress((void**)&hc,   g_hc);
    cudaGetSymbolAddress((void**)&h1,   g_h1);
    cudaGetSymbolAddress((void**)&h1c,  g_h1c);
    cudaGetSymbolAddress((void**)&wqc,  g_wqc);
    cudaGetSymbolAddress((void**)&wkc,  g_wkc);
    cudaGetSymbolAddress((void**)&wvc,  g_wvc);
    cudaGetSymbolAddress((void**)&wrc,  g_wrc);
    cudaGetSymbolAddress((void**)&woc,  g_woc);
    cudaGetSymbolAddress((void**)&w1c,  g_w1c);
    cudaGetSymbolAddress((void**)&w2c,  g_w2c);
    cudaGetSymbolAddress((void**)&memc, g_memc);
    cudaGetSymbolAddress((void**)&xc,   g_xc);

    cudaFuncSetAttribute(fused_attn_split, cudaFuncAttributeMaxDynamicSharedMemorySize,
                         SMEM_ATTN_BYTES);

    // single flattened convert launch
    {
        const int nw = (LL * DDd * DDd) / 1024;
        const int nf = (LL * DDd * FFf) / 1024;
        const int nm = (LL * BB * MMm * DDd) / 1024;
        const int nx = (BB * SSq * DDd) / 1024;
        CvtP p;
        const float* ins[9]  = {Wq, Wk, Wv, Wr, Wo, W1, W2, memory, x};
        float*       outs[9] = {wqc, wkc, wvc, wrc, woc, w1c, w2c, memc, xc};
        int          cnts[9] = {nw, nw, nw, nw, nw, nf, nf, nm, nx};
        int acc = 0;
        for (int j = 0; j < 9; j++) {
            p.in[j] = ins[j]; p.out[j] = outs[j];
            p.cum[j] = acc; acc += cnts[j];
        }
        p.cum[9] = acc;
        cvt_all9<<<acc, 256>>>(p);
    }

    pos_kernel<<<(TTt * (DDd / 2) + 255) / 256, 256>>>(pos);

    const float* hcur  = x;
    const float* hcurc = xc;
    for (int l = 0; l < LL; l++) {
        // q/k/v/r grouped (V written directly transposed), 384 CTAs
        dim3 gG(DDd / 128, 48);
        grouped_qkvr<<<gG, 256>>>(hcurc, memc + (size_t)l * BB * MMm * DDd, pos,
                                  wqc + (size_t)l * DDd * DDd, wkc + (size_t)l * DDd * DDd,
                                  wvc + (size_t)l * DDd * DDd, wrc + (size_t)l * DDd * DDd,
                                  q, k, vt, r);

        // split-T flash attention: NZ=4 partitions, 2048 CTAs
        dim3 gA(SSq / SMT, BB * HHh, NZ);
        fused_attn_split<<<gA, 256, SMEM_ATTN_BYTES>>>(
            q, k, vt, r, rwb + (size_t)l * HHh * DKk, rrb + (size_t)l * HHh * DKk,
            tmp, tmp2, tmp3, tmp4, pm, ps);
        attn_combine<<<(BB * SSq * DDd / 4 + 255) / 256, 256>>>(
            tmp, tmp2, tmp3, tmp4, pm, ps, attn);

        dim3 gO(DDd / 128, (BB * SSq) / 64, 2);
        tc_gemm_splitk<64, 4><<<gO, 256>>>(attn, woc + (size_t)l * DDd * DDd,
                                           tmp, tmp2, DDd, DDd, nullptr);
        ln_kernel2<<<BB * SSq, 256>>>(tmp, tmp2, hcur,
                                      ln1g + l * DDd, ln1b + l * DDd, h1, h1c);

        dim3 gF1(FFf / 128, (BB * SSq) / 128);
        tc_gemm_k<128, 4><<<gF1, 256>>>(h1c, w1c + (size_t)l * DDd * FFf, ff,
                                        FFf, DDd, 1.f, b1 + l * FFf, 1, 1);
        dim3 gF2(DDd / 128, (BB * SSq) / 64, 2);
        tc_gemm_splitk<64, 4><<<gF2, 256>>>(ff, w2c + (size_t)l * FFf * DDd,
                                            tmp, tmp2, DDd, FFf, b2 + l * DDd);

        if (l == LL - 1) {
            ln_kernel2<<<BB * SSq, 256>>>(tmp, tmp2, h1,
                                          ln2g + l * DDd, ln2b + l * DDd, out, nullptr);
        } else {
            ln_kernel2<<<BB * SSq, 256>>>(tmp, tmp2, h1,
                                          ln2g + l * DDd, ln2b + l * DDd, h, hc);
            hcur = h;
            hcurc = hc;
        }
    }
}